// round 14
// baseline (speedup 1.0000x reference)
#include <cuda_runtime.h>
#include <cuda_fp16.h>
#include <math.h>

#define NB   4
#define NC   64
#define FSZ  65536            // F*S
#define CFS  4194304          // C*F*S
#define TPIX 64               // pixels per tile
#define PAD  68               // smem row stride: all 16B patterns hit 4-phase minimum
#define EPSV 1e-5

// ---------------- scratch (no allocs allowed) ----------------
__device__ double g_acc[16];                 // per batch: {sx, sxx, sy, syy}
__device__ float  g_p[NB * NC];              // post-GLU channel sums
__device__ __align__(16) __half g_u[(size_t)NB * CFS];  // post-GLU activations, fp16, [b][ch][px]
// precomputed tf32 A-fragments, [kt*256 + tid] (identical for every block)
__device__ uint4  g_W1f[8 * 256];
__device__ uint4  g_W2f[8 * 256];
__device__ uint4  g_W3f[8 * 256];
__device__ uint4  g_W4f[8 * 256];

// ---------------- helpers ----------------
__device__ __forceinline__ unsigned f2tf(float f) {
    unsigned u;
    asm("cvt.rna.tf32.f32 %0, %1;" : "=r"(u) : "f"(f));
    return u;
}
__device__ __forceinline__ void mma8(float acc[4], unsigned a0, unsigned a1,
                                     unsigned a2, unsigned a3,
                                     unsigned b0, unsigned b1) {
    asm volatile(
        "mma.sync.aligned.m16n8k8.row.col.f32.tf32.tf32.f32 "
        "{%0,%1,%2,%3},{%4,%5,%6,%7},{%8,%9},{%0,%1,%2,%3};\n"
        : "+f"(acc[0]), "+f"(acc[1]), "+f"(acc[2]), "+f"(acc[3])
        : "r"(a0), "r"(a1), "r"(a2), "r"(a3), "r"(b0), "r"(b1));
}
__device__ __forceinline__ float sigm(float v) { return 1.f / (1.f + __expf(-v)); }

// ---------------- K0: zero accumulators + precompute weight fragments ----------------
__global__ void k_init(const float* __restrict__ W1, const float* __restrict__ W2,
                       const float* __restrict__ W3, const float* __restrict__ W4) {
    int tid = threadIdx.x, w = tid >> 5, lane = tid & 31;
    int blk = blockIdx.x;
    if (blk == 0) {
        if (tid < 16) g_acc[tid] = 0.0;
        g_p[tid] = 0.f;
        return;
    }
    int gq = lane >> 2, kc = lane & 3;
    if (blk == 1 || blk == 3) {            // br-role fragments: rows (8w+gq, +64)
        const float* W = (blk == 1) ? W1 : W3;
        uint4* dst = (blk == 1) ? g_W1f : g_W3f;
        int ra = 8 * w + gq, rg = ra + 64;
#pragma unroll
        for (int kt = 0; kt < 8; ++kt) {
            int k0 = kt * 8 + kc;
            uint4 v;
            v.x = f2tf(W[ra * 64 + k0]);
            v.y = f2tf(W[rg * 64 + k0]);
            v.z = f2tf(W[ra * 64 + k0 + 4]);
            v.w = f2tf(W[rg * 64 + k0 + 4]);
            dst[kt * 256 + tid] = v;
        }
    } else {                                // y-role fragments: rows (mt*16+gq, +8)
        const float* W = (blk == 2) ? W2 : W4;
        uint4* dst = (blk == 2) ? g_W2f : g_W4f;
        int mt = w & 3;
        int r0 = mt * 16 + gq, r1 = r0 + 8;
#pragma unroll
        for (int kt = 0; kt < 8; ++kt) {
            int k0 = kt * 8 + kc;
            uint4 v;
            v.x = f2tf(W[r0 * 64 + k0]);
            v.y = f2tf(W[r1 * 64 + k0]);
            v.z = f2tf(W[r0 * 64 + k0 + 4]);
            v.w = f2tf(W[r1 * 64 + k0 + 4]);
            dst[kt * 256 + tid] = v;
        }
    }
}

// ---------------- K1: LN1 stats ----------------
__global__ __launch_bounds__(256) void k_stats1(const float* __restrict__ x) {
    int bat = blockIdx.x >> 9;
    int chunk = blockIdx.x & 511;
    size_t base = (size_t)bat * CFS + (size_t)chunk * 8192;
    float s = 0.f, ss = 0.f;
#pragma unroll
    for (int it = 0; it < 8; ++it) {
        float4 v = *(const float4*)(x + base + (size_t)(threadIdx.x + 256 * it) * 4);
        s  += (v.x + v.y) + (v.z + v.w);
        ss += (v.x * v.x + v.y * v.y) + (v.z * v.z + v.w * v.w);
    }
#pragma unroll
    for (int o = 16; o; o >>= 1) {
        s  += __shfl_xor_sync(0xffffffffu, s,  o);
        ss += __shfl_xor_sync(0xffffffffu, ss, o);
    }
    __shared__ float red[16];
    int w = threadIdx.x >> 5, lane = threadIdx.x & 31;
    if (!lane) { red[w] = s; red[8 + w] = ss; }
    __syncthreads();
    if (threadIdx.x == 0) {
        float S = 0.f, SS = 0.f;
#pragma unroll
        for (int i = 0; i < 8; ++i) { S += red[i]; SS += red[8 + i]; }
        atomicAdd(&g_acc[bat * 4 + 0], (double)S);
        atomicAdd(&g_acc[bat * 4 + 1], (double)SS);
    }
}

// ---------------- K2: LN1 -> GEMM1 -> dw affine -> GLU -> u(fp16), accumulate p ----------------
// n-map: mma tile nt (0..7), frag n-pos p (0..7) -> px = 8p + nt
__global__ __launch_bounds__(256, 4) void k_br1(
    const float* __restrict__ x,  const float* __restrict__ lnw,
    const float* __restrict__ lnb,
    const float* __restrict__ pb1, const float* __restrict__ dww,
    const float* __restrict__ dwb) {
    __shared__ float sm[NC * PAD];
    __shared__ float st[2];
    int tid = threadIdx.x, w = tid >> 5, lane = tid & 31;
    int bat = blockIdx.x >> 10;
    int tile = blockIdx.x & 1023;
    size_t base  = (size_t)bat * CFS + (size_t)tile * TPIX;
    size_t pbase = (size_t)tile * TPIX;                      // LN params: NO batch dim
    if (tid == 0) {
        double m = g_acc[bat * 4 + 0] * (1.0 / (double)CFS);
        double v = g_acc[bat * 4 + 1] * (1.0 / (double)CFS) - m * m;
        st[0] = (float)m;
        st[1] = (float)(1.0 / sqrt(v + EPSV));
    }
    __syncthreads();
    float m1 = st[0], r1 = st[1];
#pragma unroll
    for (int it = 0; it < 4; ++it) {
        int e = (tid + 256 * it) * 4;
        int row = e >> 6, col = e & 63;
        size_t g  = base  + (size_t)row * FSZ + col;
        size_t gp = pbase + (size_t)row * FSZ + col;
        float4 xv = *(const float4*)(x + g);
        float4 wv = *(const float4*)(lnw + gp);
        float4 bv = *(const float4*)(lnb + gp);
        float4 o;
        o.x = __uint_as_float(f2tf(fmaf((xv.x - m1) * r1, wv.x, bv.x)));
        o.y = __uint_as_float(f2tf(fmaf((xv.y - m1) * r1, wv.y, bv.y)));
        o.z = __uint_as_float(f2tf(fmaf((xv.z - m1) * r1, wv.z, bv.z)));
        o.w = __uint_as_float(f2tf(fmaf((xv.w - m1) * r1, wv.w, bv.w)));
        *(float4*)(sm + row * PAD + col) = o;
    }
    __syncthreads();
    int gq = lane >> 2, kc = lane & 3;
    int ra = 8 * w + gq, rg = ra + 64;
    float acc[8][4];
#pragma unroll
    for (int i = 0; i < 8; ++i)
#pragma unroll
        for (int j = 0; j < 4; ++j) acc[i][j] = 0.f;
#pragma unroll
    for (int kt = 0; kt < 8; ++kt) {
        uint4 A = g_W1f[kt * 256 + tid];
        int kr = kt * 8 + kc;
        const float* br0 = sm + kr * PAD + gq * 8;
        const float* br1p = sm + (kr + 4) * PAD + gq * 8;
        float4 b0 = *(const float4*)br0;
        float4 b1 = *(const float4*)br1p;
        mma8(acc[0], A.x, A.y, A.z, A.w, __float_as_uint(b0.x), __float_as_uint(b1.x));
        mma8(acc[1], A.x, A.y, A.z, A.w, __float_as_uint(b0.y), __float_as_uint(b1.y));
        mma8(acc[2], A.x, A.y, A.z, A.w, __float_as_uint(b0.z), __float_as_uint(b1.z));
        mma8(acc[3], A.x, A.y, A.z, A.w, __float_as_uint(b0.w), __float_as_uint(b1.w));
        b0 = *(const float4*)(br0 + 4);
        b1 = *(const float4*)(br1p + 4);
        mma8(acc[4], A.x, A.y, A.z, A.w, __float_as_uint(b0.x), __float_as_uint(b1.x));
        mma8(acc[5], A.x, A.y, A.z, A.w, __float_as_uint(b0.y), __float_as_uint(b1.y));
        mma8(acc[6], A.x, A.y, A.z, A.w, __float_as_uint(b0.z), __float_as_uint(b1.z));
        mma8(acc[7], A.x, A.y, A.z, A.w, __float_as_uint(b0.w), __float_as_uint(b1.w));
    }
    // epilogue: c-frag col p = 2kc+j -> px = 8p + nt = 16kc + 8j + nt
    float b1a = pb1[ra], b1g = pb1[rg];
    float dwa = dww[ra], dba = dwb[ra], dwg = dww[rg], dbg = dwb[rg];
    __syncthreads();   // all warps done reading sm
    float psum = 0.f;
#pragma unroll
    for (int j = 0; j < 2; ++j) {
        int px0 = 16 * kc + 8 * j;
        float4 ua, ub;
        {
            float u0 = fmaf(acc[0][j] + b1a, dwa, dba) * sigm(fmaf(acc[0][2 + j] + b1g, dwg, dbg));
            float u1 = fmaf(acc[1][j] + b1a, dwa, dba) * sigm(fmaf(acc[1][2 + j] + b1g, dwg, dbg));
            float u2 = fmaf(acc[2][j] + b1a, dwa, dba) * sigm(fmaf(acc[2][2 + j] + b1g, dwg, dbg));
            float u3 = fmaf(acc[3][j] + b1a, dwa, dba) * sigm(fmaf(acc[3][2 + j] + b1g, dwg, dbg));
            float u4 = fmaf(acc[4][j] + b1a, dwa, dba) * sigm(fmaf(acc[4][2 + j] + b1g, dwg, dbg));
            float u5 = fmaf(acc[5][j] + b1a, dwa, dba) * sigm(fmaf(acc[5][2 + j] + b1g, dwg, dbg));
            float u6 = fmaf(acc[6][j] + b1a, dwa, dba) * sigm(fmaf(acc[6][2 + j] + b1g, dwg, dbg));
            float u7 = fmaf(acc[7][j] + b1a, dwa, dba) * sigm(fmaf(acc[7][2 + j] + b1g, dwg, dbg));
            ua = make_float4(u0, u1, u2, u3);
            ub = make_float4(u4, u5, u6, u7);
            psum += ((u0 + u1) + (u2 + u3)) + ((u4 + u5) + (u6 + u7));
        }
        *(float4*)(sm + ra * PAD + px0)     = ua;
        *(float4*)(sm + ra * PAD + px0 + 4) = ub;
    }
    psum += __shfl_xor_sync(0xffffffffu, psum, 1);
    psum += __shfl_xor_sync(0xffffffffu, psum, 2);
    if (kc == 0) atomicAdd(&g_p[bat * 64 + ra], psum);
    __syncthreads();
    // write u as fp16, [ch][px] geometry (uint2 = 4 halves)
#pragma unroll
    for (int it = 0; it < 4; ++it) {
        int e = (tid + 256 * it) * 4;
        int row = e >> 6, col = e & 63;
        float4 v = *(float4*)(sm + row * PAD + col);
        __half2 h0 = __floats2half2_rn(v.x, v.y);
        __half2 h1 = __floats2half2_rn(v.z, v.w);
        uint2 o;
        o.x = *(unsigned*)&h0;
        o.y = *(unsigned*)&h1;
        *(uint2*)(g_u + base + (size_t)row * FSZ + col) = o;
    }
}

// ---------------- K3: SE gate + y = W2@(u*s)+b2+x ; LN2 stats ----------------
// n-map: tile nt (0..3), frag pos p -> px = half*32 + 4p + nt
__global__ __launch_bounds__(256, 5) void k_y(
    const float* __restrict__ x,
    const float* __restrict__ pb2,
    const float* __restrict__ aw1, const float* __restrict__ ab1,
    const float* __restrict__ aw2, const float* __restrict__ ab2,
    float* __restrict__ yo) {
    __shared__ float smu[NC * PAD];
    __shared__ float smx[NC * PAD];
    __shared__ float ssg[64], sp[64], sh[64];
    __shared__ float red[16];
    int tid = threadIdx.x, w = tid >> 5, lane = tid & 31;
    int bat = blockIdx.x >> 10;
    int tile = blockIdx.x & 1023;
    size_t base = (size_t)bat * CFS + (size_t)tile * TPIX;
    // ---- SE gate, warp-cooperative ----
    if (tid < 64) sp[tid] = g_p[bat * 64 + tid] * (1.f / 65536.f);
    __syncthreads();
    {
        int gq = lane >> 2, t = lane & 3;
        int c = 8 * w + gq;
        const float4* a1 = (const float4*)(aw1 + c * 64 + t * 16);
        float part = 0.f;
#pragma unroll
        for (int q = 0; q < 4; ++q) {
            float4 wv = a1[q];
            int j = t * 16 + q * 4;
            part += wv.x * sp[j] + wv.y * sp[j + 1] + wv.z * sp[j + 2] + wv.w * sp[j + 3];
        }
        part += __shfl_xor_sync(0xffffffffu, part, 1);
        part += __shfl_xor_sync(0xffffffffu, part, 2);
        if (t == 0) sh[c] = fmaxf(part + ab1[c], 0.f);
        __syncthreads();
        const float4* a2 = (const float4*)(aw2 + c * 64 + t * 16);
        part = 0.f;
#pragma unroll
        for (int q = 0; q < 4; ++q) {
            float4 wv = a2[q];
            int j = t * 16 + q * 4;
            part += wv.x * sh[j] + wv.y * sh[j + 1] + wv.z * sh[j + 2] + wv.w * sh[j + 3];
        }
        part += __shfl_xor_sync(0xffffffffu, part, 1);
        part += __shfl_xor_sync(0xffffffffu, part, 2);
        if (t == 0) ssg[c] = sigm(part + ab2[c]);
    }
    __syncthreads();
#pragma unroll
    for (int it = 0; it < 4; ++it) {
        int e = (tid + 256 * it) * 4;
        int row = e >> 6, col = e & 63;
        size_t g = base + (size_t)row * FSZ + col;
        uint2 uv = *(const uint2*)(g_u + g);
        float2 f0 = __half22float2(*(__half2*)&uv.x);
        float2 f1 = __half22float2(*(__half2*)&uv.y);
        float4 xv = *(const float4*)(x + g);
        float sg = ssg[row];
        float4 o;
        o.x = __uint_as_float(f2tf(f0.x * sg));
        o.y = __uint_as_float(f2tf(f0.y * sg));
        o.z = __uint_as_float(f2tf(f1.x * sg));
        o.w = __uint_as_float(f2tf(f1.y * sg));
        *(float4*)(smu + row * PAD + col) = o;
        *(float4*)(smx + row * PAD + col) = xv;
    }
    __syncthreads();
    int mt = w & 3, half = w >> 2;
    int gq = lane >> 2, kc = lane & 3;
    int r0 = mt * 16 + gq, r1r = r0 + 8;
    float acc[4][4];
#pragma unroll
    for (int i = 0; i < 4; ++i)
#pragma unroll
        for (int j = 0; j < 4; ++j) acc[i][j] = 0.f;
#pragma unroll
    for (int kt = 0; kt < 8; ++kt) {
        uint4 A = g_W2f[kt * 256 + tid];
        int kr = kt * 8 + kc;
        float4 b0 = *(const float4*)(smu + kr * PAD + half * 32 + gq * 4);
        float4 b1 = *(const float4*)(smu + (kr + 4) * PAD + half * 32 + gq * 4);
        mma8(acc[0], A.x, A.y, A.z, A.w, __float_as_uint(b0.x), __float_as_uint(b1.x));
        mma8(acc[1], A.x, A.y, A.z, A.w, __float_as_uint(b0.y), __float_as_uint(b1.y));
        mma8(acc[2], A.x, A.y, A.z, A.w, __float_as_uint(b0.z), __float_as_uint(b1.z));
        mma8(acc[3], A.x, A.y, A.z, A.w, __float_as_uint(b0.w), __float_as_uint(b1.w));
    }
    float bc0 = pb2[r0], bc1 = pb2[r1r];
    float sy = 0.f, syy = 0.f;
    // epilogue: col p = 2kc+j -> px = half*32 + 8kc + 4j + nt
#pragma unroll
    for (int j = 0; j < 2; ++j) {
        int px0 = half * 32 + 8 * kc + 4 * j;
        float4 xv0 = *(float4*)(smx + r0  * PAD + px0);
        float4 xv1 = *(float4*)(smx + r1r * PAD + px0);
        float4 y0, y1;
        y0.x = acc[0][j] + bc0 + xv0.x;
        y0.y = acc[1][j] + bc0 + xv0.y;
        y0.z = acc[2][j] + bc0 + xv0.z;
        y0.w = acc[3][j] + bc0 + xv0.w;
        y1.x = acc[0][2 + j] + bc1 + xv1.x;
        y1.y = acc[1][2 + j] + bc1 + xv1.y;
        y1.z = acc[2][2 + j] + bc1 + xv1.z;
        y1.w = acc[3][2 + j] + bc1 + xv1.w;
        *(float4*)(smx + r0  * PAD + px0) = y0;
        *(float4*)(smx + r1r * PAD + px0) = y1;
        sy  += ((y0.x + y0.y) + (y0.z + y0.w)) + ((y1.x + y1.y) + (y1.z + y1.w));
        syy += (y0.x * y0.x + y0.y * y0.y) + (y0.z * y0.z + y0.w * y0.w)
             + (y1.x * y1.x + y1.y * y1.y) + (y1.z * y1.z + y1.w * y1.w);
    }
#pragma unroll
    for (int o = 16; o; o >>= 1) {
        sy  += __shfl_xor_sync(0xffffffffu, sy,  o);
        syy += __shfl_xor_sync(0xffffffffu, syy, o);
    }
    if (!lane) { red[w] = sy; red[8 + w] = syy; }
    __syncthreads();
    if (tid == 0) {
        float S = 0.f, SS = 0.f;
#pragma unroll
        for (int i = 0; i < 8; ++i) { S += red[i]; SS += red[8 + i]; }
        atomicAdd(&g_acc[bat * 4 + 2], (double)S);
        atomicAdd(&g_acc[bat * 4 + 3], (double)SS);
    }
#pragma unroll
    for (int it = 0; it < 4; ++it) {
        int e = (tid + 256 * it) * 4;
        int row = e >> 6, col = e & 63;
        *(float4*)(yo + base + (size_t)row * FSZ + col) = *(float4*)(smx + row * PAD + col);
    }
}

// ---------------- K4: LN2 -> GEMM3 -> GLU -> GEMM4 -> +y ----------------
__global__ __launch_bounds__(256, 4) void k_br2(
    const float* __restrict__ lnw, const float* __restrict__ lnb,
    const float* __restrict__ pb3, const float* __restrict__ pb4,
    float* __restrict__ io) {
    __shared__ float smy[NC * PAD];
    __shared__ float smb[NC * PAD];
    __shared__ float st[2];
    int tid = threadIdx.x, w = tid >> 5, lane = tid & 31;
    int bat = blockIdx.x >> 10;
    int tile = blockIdx.x & 1023;
    size_t base  = (size_t)bat * CFS + (size_t)tile * TPIX;
    size_t pbase = (size_t)tile * TPIX;                      // LN params: NO batch dim
    if (tid == 0) {
        double m = g_acc[bat * 4 + 2] * (1.0 / (double)CFS);
        double v = g_acc[bat * 4 + 3] * (1.0 / (double)CFS) - m * m;
        st[0] = (float)m;
        st[1] = (float)(1.0 / sqrt(v + EPSV));
    }
    __syncthreads();
    float m2 = st[0], r2 = st[1];
#pragma unroll
    for (int it = 0; it < 4; ++it) {
        int e = (tid + 256 * it) * 4;
        int row = e >> 6, col = e & 63;
        size_t g  = base  + (size_t)row * FSZ + col;
        size_t gp = pbase + (size_t)row * FSZ + col;
        float4 yv = *(const float4*)(io + g);
        float4 wv = *(const float4*)(lnw + gp);
        float4 bv = *(const float4*)(lnb + gp);
        *(float4*)(smy + row * PAD + col) = yv;
        float4 o;
        o.x = __uint_as_float(f2tf(fmaf((yv.x - m2) * r2, wv.x, bv.x)));
        o.y = __uint_as_float(f2tf(fmaf((yv.y - m2) * r2, wv.y, bv.y)));
        o.z = __uint_as_float(f2tf(fmaf((yv.z - m2) * r2, wv.z, bv.z)));
        o.w = __uint_as_float(f2tf(fmaf((yv.w - m2) * r2, wv.w, bv.w)));
        *(float4*)(smb + row * PAD + col) = o;
    }
    __syncthreads();
    int gq = lane >> 2, kc = lane & 3;
    // GEMM3 (128x64): n-map px = 8p + nt
    int ra = 8 * w + gq, rg = ra + 64;
    {
        float acc[8][4];
#pragma unroll
        for (int i = 0; i < 8; ++i)
#pragma unroll
            for (int j = 0; j < 4; ++j) acc[i][j] = 0.f;
#pragma unroll
        for (int kt = 0; kt < 8; ++kt) {
            uint4 A = g_W3f[kt * 256 + tid];
            int kr = kt * 8 + kc;
            const float* br0 = smb + kr * PAD + gq * 8;
            const float* br1p = smb + (kr + 4) * PAD + gq * 8;
            float4 b0 = *(const float4*)br0;
            float4 b1 = *(const float4*)br1p;
            mma8(acc[0], A.x, A.y, A.z, A.w, __float_as_uint(b0.x), __float_as_uint(b1.x));
            mma8(acc[1], A.x, A.y, A.z, A.w, __float_as_uint(b0.y), __float_as_uint(b1.y));
            mma8(acc[2], A.x, A.y, A.z, A.w, __float_as_uint(b0.z), __float_as_uint(b1.z));
            mma8(acc[3], A.x, A.y, A.z, A.w, __float_as_uint(b0.w), __float_as_uint(b1.w));
            b0 = *(const float4*)(br0 + 4);
            b1 = *(const float4*)(br1p + 4);
            mma8(acc[4], A.x, A.y, A.z, A.w, __float_as_uint(b0.x), __float_as_uint(b1.x));
            mma8(acc[5], A.x, A.y, A.z, A.w, __float_as_uint(b0.y), __float_as_uint(b1.y));
            mma8(acc[6], A.x, A.y, A.z, A.w, __float_as_uint(b0.z), __float_as_uint(b1.z));
            mma8(acc[7], A.x, A.y, A.z, A.w, __float_as_uint(b0.w), __float_as_uint(b1.w));
        }
        float b3a = pb3[ra], b3g = pb3[rg];
        __syncthreads();  // done reading ln2 from smb
#pragma unroll
        for (int j = 0; j < 2; ++j) {
            int px0 = 16 * kc + 8 * j;
            float4 ua, ub;
            ua.x = __uint_as_float(f2tf((acc[0][j] + b3a) * sigm(acc[0][2 + j] + b3g)));
            ua.y = __uint_as_float(f2tf((acc[1][j] + b3a) * sigm(acc[1][2 + j] + b3g)));
            ua.z = __uint_as_float(f2tf((acc[2][j] + b3a) * sigm(acc[2][2 + j] + b3g)));
            ua.w = __uint_as_float(f2tf((acc[3][j] + b3a) * sigm(acc[3][2 + j] + b3g)));
            ub.x = __uint_as_float(f2tf((acc[4][j] + b3a) * sigm(acc[4][2 + j] + b3g)));
            ub.y = __uint_as_float(f2tf((acc[5][j] + b3a) * sigm(acc[5][2 + j] + b3g)));
            ub.z = __uint_as_float(f2tf((acc[6][j] + b3a) * sigm(acc[6][2 + j] + b3g)));
            ub.w = __uint_as_float(f2tf((acc[7][j] + b3a) * sigm(acc[7][2 + j] + b3g)));
            *(float4*)(smb + ra * PAD + px0)     = ua;
            *(float4*)(smb + ra * PAD + px0 + 4) = ub;
        }
        __syncthreads();
    }
    // GEMM4 (64x64): n-map px = half*32 + 4p + nt; out = W4@u2 + b4 + y (in-place smy)
    int mt = w & 3, half = w >> 2;
    int r0 = mt * 16 + gq, r1r = r0 + 8;
    float ac2[4][4];
#pragma unroll
    for (int i = 0; i < 4; ++i)
#pragma unroll
        for (int j = 0; j < 4; ++j) ac2[i][j] = 0.f;
#pragma unroll
    for (int kt = 0; kt < 8; ++kt) {
        uint4 A = g_W4f[kt * 256 + tid];
        int kr = kt * 8 + kc;
        float4 b0 = *(const float4*)(smb + kr * PAD + half * 32 + gq * 4);
        float4 b1 = *(const float4*)(smb + (kr + 4) * PAD + half * 32 + gq * 4);
        mma8(ac2[0], A.x, A.y, A.z, A.w, __float_as_uint(b0.x), __float_as_uint(b1.x));
        mma8(ac2[1], A.x, A.y, A.z, A.w, __float_as_uint(b0.y), __float_as_uint(b1.y));
        mma8(ac2[2], A.x, A.y, A.z, A.w, __float_as_uint(b0.z), __float_as_uint(b1.z));
        mma8(ac2[3], A.x, A.y, A.z, A.w, __float_as_uint(b0.w), __float_as_uint(b1.w));
    }
    float b40 = pb4[r0], b41 = pb4[r1r];
#pragma unroll
    for (int j = 0; j < 2; ++j) {
        int px0 = half * 32 + 8 * kc + 4 * j;
        float4 y0 = *(float4*)(smy + r0  * PAD + px0);
        float4 y1 = *(float4*)(smy + r1r * PAD + px0);
        y0.x += ac2[0][j] + b40;
        y0.y += ac2[1][j] + b40;
        y0.z += ac2[2][j] + b40;
        y0.w += ac2[3][j] + b40;
        y1.x += ac2[0][2 + j] + b41;
        y1.y += ac2[1][2 + j] + b41;
        y1.z += ac2[2][2 + j] + b41;
        y1.w += ac2[3][2 + j] + b41;
        *(float4*)(smy + r0  * PAD + px0) = y0;
        *(float4*)(smy + r1r * PAD + px0) = y1;
    }
    __syncthreads();
#pragma unroll
    for (int it = 0; it < 4; ++it) {
        int e = (tid + 256 * it) * 4;
        int row = e >> 6, col = e & 63;
        *(float4*)(io + base + (size_t)row * FSZ + col) = *(float4*)(smy + row * PAD + col);
    }
}

// ---------------- launch ----------------
extern "C" void kernel_launch(void* const* d_in, const int* in_sizes, int n_in,
                              void* d_out, int out_size) {
    const float* x   = (const float*)d_in[0];
    const float* l1w = (const float*)d_in[1];
    const float* l1b = (const float*)d_in[2];
    const float* l2w = (const float*)d_in[3];
    const float* l2b = (const float*)d_in[4];
    const float* W1  = (const float*)d_in[5];
    const float* b1  = (const float*)d_in[6];
    const float* dww = (const float*)d_in[7];
    const float* dwb = (const float*)d_in[8];
    const float* aw1 = (const float*)d_in[9];
    const float* ab1 = (const float*)d_in[10];
    const float* aw2 = (const float*)d_in[11];
    const float* ab2 = (const float*)d_in[12];
    const float* W2  = (const float*)d_in[13];
    const float* b2  = (const float*)d_in[14];
    const float* W3  = (const float*)d_in[15];
    const float* b3  = (const float*)d_in[16];
    const float* W4  = (const float*)d_in[17];
    const float* b4  = (const float*)d_in[18];
    float* out = (float*)d_out;

    k_init  <<<5, 256>>>(W1, W2, W3, W4);
    k_stats1<<<NB * 512, 256>>>(x);
    k_br1   <<<NB * 1024, 256>>>(x, l1w, l1b, b1, dww, dwb);
    k_y     <<<NB * 1024, 256>>>(x, b2, aw1, ab1, aw2, ab2, out);
    k_br2   <<<NB * 1024, 256>>>(l2w, l2b, b3, b4, out);
}

// round 17
// speedup vs baseline: 1.4268x; 1.4268x over previous
#include <cuda_runtime.h>
#include <cuda_fp16.h>
#include <math.h>

#define NB   4
#define FSZ  65536            // F*S
#define CFS  4194304          // C*F*S
#define PW   72               // half2 words per kw-row in sB (>=64; 72%32==8 -> conflict-free)
#define PADX 68               // fp32 residual buffer row stride
#define EPSV 1e-5

// ---------------- scratch (no allocs allowed) ----------------
__device__ double g_acc[16];                 // per batch: {sx, sxx, sy, syy}
__device__ float  g_p[NB * 64];              // post-GLU channel sums
// u pre-paired: word [b][kw][px] = half2(u[2kw][px], u[2kw+1][px])
__device__ __align__(16) unsigned g_u[(size_t)NB * 32 * FSZ];
// precomputed fp16 A-fragments, [kt*256 + tid]
__device__ uint4  g_W1f[4 * 256];
__device__ uint4  g_W2f[4 * 256];
__device__ uint4  g_W3f[4 * 256];
__device__ uint4  g_W4f[4 * 256];

// ---------------- helpers ----------------
__device__ __forceinline__ unsigned packh2(float a, float b) {
    __half2 h = __floats2half2_rn(a, b);
    return *(unsigned*)&h;
}
__device__ __forceinline__ void mma16(float acc[4], unsigned a0, unsigned a1,
                                      unsigned a2, unsigned a3,
                                      unsigned b0, unsigned b1) {
    asm volatile(
        "mma.sync.aligned.m16n8k16.row.col.f32.f16.f16.f32 "
        "{%0,%1,%2,%3},{%4,%5,%6,%7},{%8,%9},{%0,%1,%2,%3};\n"
        : "+f"(acc[0]), "+f"(acc[1]), "+f"(acc[2]), "+f"(acc[3])
        : "r"(a0), "r"(a1), "r"(a2), "r"(a3), "r"(b0), "r"(b1));
}
__device__ __forceinline__ float sigm(float v) { return 1.f / (1.f + __expf(-v)); }
__device__ __forceinline__ unsigned sc_h2(unsigned hw, float s0, float s1) {
    __half2 h = *(__half2*)&hw;
    float2 f = __half22float2(h);
    return packh2(f.x * s0, f.y * s1);
}

// ---------------- K0: zero accumulators + precompute fp16 weight fragments ----------------
__global__ void k_init(const float* __restrict__ W1, const float* __restrict__ W2,
                       const float* __restrict__ W3, const float* __restrict__ W4) {
    int tid = threadIdx.x, w = tid >> 5, lane = tid & 31;
    int blk = blockIdx.x;
    if (blk == 0) {
        if (tid < 16) g_acc[tid] = 0.0;
        g_p[tid] = 0.f;
        return;
    }
    int gq = lane >> 2, kc = lane & 3;
    int chA, chB;
    const float* W;
    uint4* dst;
    if (blk == 1 || blk == 3) {            // br-role: rows (8w+gq, +64)
        W = (blk == 1) ? W1 : W3;
        dst = (blk == 1) ? g_W1f : g_W3f;
        chA = 8 * w + gq; chB = chA + 64;
    } else {                                // y-role: rows (mt*16+gq, +8)
        W = (blk == 2) ? W2 : W4;
        dst = (blk == 2) ? g_W2f : g_W4f;
        int mt = w & 3;
        chA = mt * 16 + gq; chB = chA + 8;
    }
#pragma unroll
    for (int kt = 0; kt < 4; ++kt) {
        int k0 = kt * 16 + 2 * kc;
        uint4 v;
        v.x = packh2(W[chA * 64 + k0],     W[chA * 64 + k0 + 1]);
        v.y = packh2(W[chB * 64 + k0],     W[chB * 64 + k0 + 1]);
        v.z = packh2(W[chA * 64 + k0 + 8], W[chA * 64 + k0 + 9]);
        v.w = packh2(W[chB * 64 + k0 + 8], W[chB * 64 + k0 + 9]);
        dst[kt * 256 + tid] = v;
    }
}

// ---------------- K1: LN1 stats ----------------
__global__ __launch_bounds__(256) void k_stats1(const float* __restrict__ x) {
    int bat = blockIdx.x >> 9;
    int chunk = blockIdx.x & 511;
    size_t base = (size_t)bat * CFS + (size_t)chunk * 8192;
    float s = 0.f, ss = 0.f;
#pragma unroll
    for (int it = 0; it < 8; ++it) {
        float4 v = *(const float4*)(x + base + (size_t)(threadIdx.x + 256 * it) * 4);
        s  += (v.x + v.y) + (v.z + v.w);
        ss += (v.x * v.x + v.y * v.y) + (v.z * v.z + v.w * v.w);
    }
#pragma unroll
    for (int o = 16; o; o >>= 1) {
        s  += __shfl_xor_sync(0xffffffffu, s,  o);
        ss += __shfl_xor_sync(0xffffffffu, ss, o);
    }
    __shared__ float red[16];
    int w = threadIdx.x >> 5, lane = threadIdx.x & 31;
    if (!lane) { red[w] = s; red[8 + w] = ss; }
    __syncthreads();
    if (threadIdx.x == 0) {
        float S = 0.f, SS = 0.f;
#pragma unroll
        for (int i = 0; i < 8; ++i) { S += red[i]; SS += red[8 + i]; }
        atomicAdd(&g_acc[bat * 4 + 0], (double)S);
        atomicAdd(&g_acc[bat * 4 + 1], (double)SS);
    }
}

// ---------------- K2: LN1 -> GEMM1(f16) -> dw affine -> GLU -> u(paired fp16); p ----------------
// n-map: tiles 0-3 -> px = 4p+nt; tiles 4-7 -> px = 32+4p+(nt-4)
__global__ __launch_bounds__(256, 4) void k_br1(
    const float* __restrict__ x,  const float* __restrict__ lnw,
    const float* __restrict__ lnb,
    const float* __restrict__ pb1, const float* __restrict__ dww,
    const float* __restrict__ dwb) {
    __shared__ __align__(16) unsigned sB[32 * PW];
    __shared__ float st[2];
    int tid = threadIdx.x, w = tid >> 5, lane = tid & 31;
    int bat = blockIdx.x >> 10;
    int tile = blockIdx.x & 1023;
    size_t base  = (size_t)bat * CFS + (size_t)tile * 64;
    size_t pbase = (size_t)tile * 64;                      // LN params: NO batch dim
    if (tid == 0) {
        double m = g_acc[bat * 4 + 0] * (1.0 / (double)CFS);
        double v = g_acc[bat * 4 + 1] * (1.0 / (double)CFS) - m * m;
        st[0] = (float)m;
        st[1] = (float)(1.0 / sqrt(v + EPSV));
    }
    __syncthreads();
    float m1 = st[0], r1 = st[1];
    {   // stage LN1 as half2 channel-pairs: thread = pixel px, 8 kw rows
        int px = tid & 63, kwg = tid >> 6;
#pragma unroll
        for (int i = 0; i < 8; ++i) {
            int kw = kwg * 8 + i;
            int c0 = 2 * kw, c1 = c0 + 1;
            size_t g0 = base  + (size_t)c0 * FSZ + px;
            size_t g1 = base  + (size_t)c1 * FSZ + px;
            size_t p0 = pbase + (size_t)c0 * FSZ + px;
            size_t p1 = pbase + (size_t)c1 * FSZ + px;
            float l0 = fmaf((x[g0] - m1) * r1, lnw[p0], lnb[p0]);
            float l1 = fmaf((x[g1] - m1) * r1, lnw[p1], lnb[p1]);
            sB[kw * PW + px] = packh2(l0, l1);
        }
    }
    __syncthreads();
    int gq = lane >> 2, kc = lane & 3;
    int chA = 8 * w + gq, chB = chA + 64;
    float acc[8][4];
#pragma unroll
    for (int i = 0; i < 8; ++i)
#pragma unroll
        for (int j = 0; j < 4; ++j) acc[i][j] = 0.f;
#pragma unroll
    for (int kt = 0; kt < 4; ++kt) {
        uint4 A = g_W1f[kt * 256 + tid];
        int kwa = 8 * kt + kc;
        const unsigned* pa = sB + kwa * PW;
        const unsigned* pb = sB + (kwa + 4) * PW;
        uint4 b0 = *(const uint4*)(pa + 4 * gq);
        uint4 b1 = *(const uint4*)(pb + 4 * gq);
        mma16(acc[0], A.x, A.y, A.z, A.w, b0.x, b1.x);
        mma16(acc[1], A.x, A.y, A.z, A.w, b0.y, b1.y);
        mma16(acc[2], A.x, A.y, A.z, A.w, b0.z, b1.z);
        mma16(acc[3], A.x, A.y, A.z, A.w, b0.w, b1.w);
        b0 = *(const uint4*)(pa + 32 + 4 * gq);
        b1 = *(const uint4*)(pb + 32 + 4 * gq);
        mma16(acc[4], A.x, A.y, A.z, A.w, b0.x, b1.x);
        mma16(acc[5], A.x, A.y, A.z, A.w, b0.y, b1.y);
        mma16(acc[6], A.x, A.y, A.z, A.w, b0.z, b1.z);
        mma16(acc[7], A.x, A.y, A.z, A.w, b0.w, b1.w);
    }
    // epilogue: +b1, dw affine, GLU (a/g in-register); pair channels via shfl; write g_u
    float b1a = pb1[chA], b1g = pb1[chB];
    float dwa = dww[chA], dba = dwb[chA], dwg = dww[chB], dbg = dwb[chB];
    int kw = chA >> 1;
    size_t ubase = ((size_t)bat * 32 + kw) * FSZ + (size_t)tile * 64;
    bool writer = ((gq & 1) == 0);
    float psum = 0.f;
#pragma unroll
    for (int j = 0; j < 2; ++j) {
        float u[8];
#pragma unroll
        for (int nt = 0; nt < 8; ++nt) {
            float a = fmaf(acc[nt][j]     + b1a, dwa, dba);
            float g = fmaf(acc[nt][2 + j] + b1g, dwg, dbg);
            u[nt] = a * sigm(g);
            psum += u[nt];
        }
        unsigned pk[8];
#pragma unroll
        for (int nt = 0; nt < 8; ++nt) {
            float o = __shfl_xor_sync(0xffffffffu, u[nt], 4);
            pk[nt] = packh2(u[nt], o);       // valid on even-gq (writer) lanes
        }
        if (writer) {
            int px0 = 8 * kc + 4 * j;
            *(uint4*)(g_u + ubase + px0)      = make_uint4(pk[0], pk[1], pk[2], pk[3]);
            *(uint4*)(g_u + ubase + 32 + px0) = make_uint4(pk[4], pk[5], pk[6], pk[7]);
        }
    }
    psum += __shfl_xor_sync(0xffffffffu, psum, 1);
    psum += __shfl_xor_sync(0xffffffffu, psum, 2);
    if (kc == 0) atomicAdd(&g_p[bat * 64 + chA], psum);
}

// ---------------- K3: SE gate + y = W2@(u*s)+b2+x ; LN2 stats ----------------
// n-map: tile nt (0..3) -> px = half*32 + 4p + nt
__global__ __launch_bounds__(256, 5) void k_y(
    const float* __restrict__ x,
    const float* __restrict__ pb2,
    const float* __restrict__ aw1, const float* __restrict__ ab1,
    const float* __restrict__ aw2, const float* __restrict__ ab2,
    float* __restrict__ yo) {
    __shared__ __align__(16) unsigned sB[32 * PW];
    __shared__ float smx[64 * PADX];
    __shared__ float ssg[64], sp[64], sh[64];
    __shared__ float red[16];
    int tid = threadIdx.x, w = tid >> 5, lane = tid & 31;
    int bat = blockIdx.x >> 10;
    int tile = blockIdx.x & 1023;
    size_t base = (size_t)bat * CFS + (size_t)tile * 64;
    int gq = lane >> 2, kc = lane & 3;
    // ---- SE gate, warp-cooperative ----
    if (tid < 64) sp[tid] = g_p[bat * 64 + tid] * (1.f / 65536.f);
    __syncthreads();
    {
        int c = 8 * w + gq;
        const float4* a1 = (const float4*)(aw1 + c * 64 + kc * 16);
        float part = 0.f;
#pragma unroll
        for (int q = 0; q < 4; ++q) {
            float4 wv = a1[q];
            int j = kc * 16 + q * 4;
            part += wv.x * sp[j] + wv.y * sp[j + 1] + wv.z * sp[j + 2] + wv.w * sp[j + 3];
        }
        part += __shfl_xor_sync(0xffffffffu, part, 1);
        part += __shfl_xor_sync(0xffffffffu, part, 2);
        if (kc == 0) sh[c] = fmaxf(part + ab1[c], 0.f);
        __syncthreads();
        const float4* a2 = (const float4*)(aw2 + c * 64 + kc * 16);
        part = 0.f;
#pragma unroll
        for (int q = 0; q < 4; ++q) {
            float4 wv = a2[q];
            int j = kc * 16 + q * 4;
            part += wv.x * sh[j] + wv.y * sh[j + 1] + wv.z * sh[j + 2] + wv.w * sh[j + 3];
        }
        part += __shfl_xor_sync(0xffffffffu, part, 1);
        part += __shfl_xor_sync(0xffffffffu, part, 2);
        if (kc == 0) ssg[c] = sigm(part + ab2[c]);
    }
    __syncthreads();
    {   // unstage u (pre-paired), scale by gate, store to sB; stage x to smx
        int kw = tid >> 3, c4 = (tid & 7) * 4;
        size_t ubase = ((size_t)bat * 32 + kw) * FSZ + (size_t)tile * 64;
        float s0 = ssg[2 * kw], s1 = ssg[2 * kw + 1];
        uint4 v0 = *(const uint4*)(g_u + ubase + c4);
        uint4 v1 = *(const uint4*)(g_u + ubase + 32 + c4);
        v0.x = sc_h2(v0.x, s0, s1); v0.y = sc_h2(v0.y, s0, s1);
        v0.z = sc_h2(v0.z, s0, s1); v0.w = sc_h2(v0.w, s0, s1);
        v1.x = sc_h2(v1.x, s0, s1); v1.y = sc_h2(v1.y, s0, s1);
        v1.z = sc_h2(v1.z, s0, s1); v1.w = sc_h2(v1.w, s0, s1);
        *(uint4*)(sB + kw * PW + c4)      = v0;
        *(uint4*)(sB + kw * PW + 32 + c4) = v1;
#pragma unroll
        for (int it = 0; it < 4; ++it) {
            int e = (tid + 256 * it) * 4;
            int row = e >> 6, col = e & 63;
            *(float4*)(smx + row * PADX + col) = *(const float4*)(x + base + (size_t)row * FSZ + col);
        }
    }
    __syncthreads();
    int mt = w & 3, half = w >> 2;
    int r0 = mt * 16 + gq, r1r = r0 + 8;
    float acc[4][4];
#pragma unroll
    for (int i = 0; i < 4; ++i)
#pragma unroll
        for (int j = 0; j < 4; ++j) acc[i][j] = 0.f;
#pragma unroll
    for (int kt = 0; kt < 4; ++kt) {
        uint4 A = g_W2f[kt * 256 + tid];
        int kwa = 8 * kt + kc;
        uint4 b0 = *(const uint4*)(sB + kwa * PW + half * 32 + 4 * gq);
        uint4 b1 = *(const uint4*)(sB + (kwa + 4) * PW + half * 32 + 4 * gq);
        mma16(acc[0], A.x, A.y, A.z, A.w, b0.x, b1.x);
        mma16(acc[1], A.x, A.y, A.z, A.w, b0.y, b1.y);
        mma16(acc[2], A.x, A.y, A.z, A.w, b0.z, b1.z);
        mma16(acc[3], A.x, A.y, A.z, A.w, b0.w, b1.w);
    }
    float bc0 = pb2[r0], bc1 = pb2[r1r];
    float sy = 0.f, syy = 0.f;
#pragma unroll
    for (int j = 0; j < 2; ++j) {
        int px0 = half * 32 + 8 * kc + 4 * j;
        float4 xv0 = *(float4*)(smx + r0  * PADX + px0);
        float4 xv1 = *(float4*)(smx + r1r * PADX + px0);
        float4 y0, y1;
        y0.x = acc[0][j] + bc0 + xv0.x;
        y0.y = acc[1][j] + bc0 + xv0.y;
        y0.z = acc[2][j] + bc0 + xv0.z;
        y0.w = acc[3][j] + bc0 + xv0.w;
        y1.x = acc[0][2 + j] + bc1 + xv1.x;
        y1.y = acc[1][2 + j] + bc1 + xv1.y;
        y1.z = acc[2][2 + j] + bc1 + xv1.z;
        y1.w = acc[3][2 + j] + bc1 + xv1.w;
        *(float4*)(smx + r0  * PADX + px0) = y0;
        *(float4*)(smx + r1r * PADX + px0) = y1;
        sy  += ((y0.x + y0.y) + (y0.z + y0.w)) + ((y1.x + y1.y) + (y1.z + y1.w));
        syy += (y0.x * y0.x + y0.y * y0.y) + (y0.z * y0.z + y0.w * y0.w)
             + (y1.x * y1.x + y1.y * y1.y) + (y1.z * y1.z + y1.w * y1.w);
    }
#pragma unroll
    for (int o = 16; o; o >>= 1) {
        sy  += __shfl_xor_sync(0xffffffffu, sy,  o);
        syy += __shfl_xor_sync(0xffffffffu, syy, o);
    }
    if (!lane) { red[w] = sy; red[8 + w] = syy; }
    __syncthreads();
    if (tid == 0) {
        float S = 0.f, SS = 0.f;
#pragma unroll
        for (int i = 0; i < 8; ++i) { S += red[i]; SS += red[8 + i]; }
        atomicAdd(&g_acc[bat * 4 + 2], (double)S);
        atomicAdd(&g_acc[bat * 4 + 3], (double)SS);
    }
#pragma unroll
    for (int it = 0; it < 4; ++it) {
        int e = (tid + 256 * it) * 4;
        int row = e >> 6, col = e & 63;
        *(float4*)(yo + base + (size_t)row * FSZ + col) = *(float4*)(smx + row * PADX + col);
    }
}

// ---------------- K4: LN2 -> GEMM3(f16) -> GLU -> GEMM4(f16) -> +y ----------------
__global__ __launch_bounds__(256, 4) void k_br2(
    const float* __restrict__ lnw, const float* __restrict__ lnb,
    const float* __restrict__ pb3, const float* __restrict__ pb4,
    float* __restrict__ io) {
    __shared__ __align__(16) unsigned sB[32 * PW];   // ln2 half2, later u2
    __shared__ float smy[64 * PADX];
    __shared__ float st[2];
    int tid = threadIdx.x, w = tid >> 5, lane = tid & 31;
    int bat = blockIdx.x >> 10;
    int tile = blockIdx.x & 1023;
    size_t base  = (size_t)bat * CFS + (size_t)tile * 64;
    size_t pbase = (size_t)tile * 64;                      // LN params: NO batch dim
    if (tid == 0) {
        double m = g_acc[bat * 4 + 2] * (1.0 / (double)CFS);
        double v = g_acc[bat * 4 + 3] * (1.0 / (double)CFS) - m * m;
        st[0] = (float)m;
        st[1] = (float)(1.0 / sqrt(v + EPSV));
    }
    __syncthreads();
    float m2 = st[0], r2 = st[1];
    {   // stage y (fp32) and LN2 (half2 pairs)
        int px = tid & 63, kwg = tid >> 6;
#pragma unroll
        for (int i = 0; i < 8; ++i) {
            int kw = kwg * 8 + i;
            int c0 = 2 * kw, c1 = c0 + 1;
            float y0 = io[base + (size_t)c0 * FSZ + px];
            float y1 = io[base + (size_t)c1 * FSZ + px];
            smy[c0 * PADX + px] = y0;
            smy[c1 * PADX + px] = y1;
            size_t p0 = pbase + (size_t)c0 * FSZ + px;
            size_t p1 = pbase + (size_t)c1 * FSZ + px;
            float l0 = fmaf((y0 - m2) * r2, lnw[p0], lnb[p0]);
            float l1 = fmaf((y1 - m2) * r2, lnw[p1], lnb[p1]);
            sB[kw * PW + px] = packh2(l0, l1);
        }
    }
    __syncthreads();
    int gq = lane >> 2, kc = lane & 3;
    // GEMM3 (128x64), GLU pairing; n-map tiles 0-3 -> 4p+nt, 4-7 -> 32+4p+(nt-4)
    int chA = 8 * w + gq, chB = chA + 64;
    {
        float acc[8][4];
#pragma unroll
        for (int i = 0; i < 8; ++i)
#pragma unroll
            for (int j = 0; j < 4; ++j) acc[i][j] = 0.f;
#pragma unroll
        for (int kt = 0; kt < 4; ++kt) {
            uint4 A = g_W3f[kt * 256 + tid];
            int kwa = 8 * kt + kc;
            const unsigned* pa = sB + kwa * PW;
            const unsigned* pb = sB + (kwa + 4) * PW;
            uint4 b0 = *(const uint4*)(pa + 4 * gq);
            uint4 b1 = *(const uint4*)(pb + 4 * gq);
            mma16(acc[0], A.x, A.y, A.z, A.w, b0.x, b1.x);
            mma16(acc[1], A.x, A.y, A.z, A.w, b0.y, b1.y);
            mma16(acc[2], A.x, A.y, A.z, A.w, b0.z, b1.z);
            mma16(acc[3], A.x, A.y, A.z, A.w, b0.w, b1.w);
            b0 = *(const uint4*)(pa + 32 + 4 * gq);
            b1 = *(const uint4*)(pb + 32 + 4 * gq);
            mma16(acc[4], A.x, A.y, A.z, A.w, b0.x, b1.x);
            mma16(acc[5], A.x, A.y, A.z, A.w, b0.y, b1.y);
            mma16(acc[6], A.x, A.y, A.z, A.w, b0.z, b1.z);
            mma16(acc[7], A.x, A.y, A.z, A.w, b0.w, b1.w);
        }
        float b3a = pb3[chA], b3g = pb3[chB];
        int kw = chA >> 1;
        bool writer = ((gq & 1) == 0);
        __syncthreads();  // all warps done reading ln2 from sB
#pragma unroll
        for (int j = 0; j < 2; ++j) {
            float u[8];
#pragma unroll
            for (int nt = 0; nt < 8; ++nt)
                u[nt] = (acc[nt][j] + b3a) * sigm(acc[nt][2 + j] + b3g);
            unsigned pk[8];
#pragma unroll
            for (int nt = 0; nt < 8; ++nt) {
                float o = __shfl_xor_sync(0xffffffffu, u[nt], 4);
                pk[nt] = packh2(u[nt], o);
            }
            if (writer) {
                int px0 = 8 * kc + 4 * j;
                *(uint4*)(sB + kw * PW + px0)      = make_uint4(pk[0], pk[1], pk[2], pk[3]);
                *(uint4*)(sB + kw * PW + 32 + px0) = make_uint4(pk[4], pk[5], pk[6], pk[7]);
            }
        }
        __syncthreads();
    }
    // GEMM4 (64x64) over u2; n-map px = half*32 + 4p + nt; out = +b4 + y (in-place smy)
    int mt = w & 3, half = w >> 2;
    int r0 = mt * 16 + gq, r1r = r0 + 8;
    float ac2[4][4];
#pragma unroll
    for (int i = 0; i < 4; ++i)
#pragma unroll
        for (int j = 0; j < 4; ++j) ac2[i][j] = 0.f;
#pragma unroll
    for (int kt = 0; kt < 4; ++kt) {
        uint4 A = g_W4f[kt * 256 + tid];
        int kwa = 8 * kt + kc;
        uint4 b0 = *(const uint4*)(sB + kwa * PW + half * 32 + 4 * gq);
        uint4 b1 = *(const uint4*)(sB + (kwa + 4) * PW + half * 32 + 4 * gq);
        mma16(ac2[0], A.x, A.y, A.z, A.w, b0.x, b1.x);
        mma16(ac2[1], A.x, A.y, A.z, A.w, b0.y, b1.y);
        mma16(ac2[2], A.x, A.y, A.z, A.w, b0.z, b1.z);
        mma16(ac2[3], A.x, A.y, A.z, A.w, b0.w, b1.w);
    }
    float b40 = pb4[r0], b41 = pb4[r1r];
#pragma unroll
    for (int j = 0; j < 2; ++j) {
        int px0 = half * 32 + 8 * kc + 4 * j;
        float4 y0 = *(float4*)(smy + r0  * PADX + px0);
        float4 y1 = *(float4*)(smy + r1r * PADX + px0);
        y0.x += ac2[0][j] + b40;
        y0.y += ac2[1][j] + b40;
        y0.z += ac2[2][j] + b40;
        y0.w += ac2[3][j] + b40;
        y1.x += ac2[0][2 + j] + b41;
        y1.y += ac2[1][2 + j] + b41;
        y1.z += ac2[2][2 + j] + b41;
        y1.w += ac2[3][2 + j] + b41;
        *(float4*)(smy + r0  * PADX + px0) = y0;
        *(float4*)(smy + r1r * PADX + px0) = y1;
    }
    __syncthreads();
#pragma unroll
    for (int it = 0; it < 4; ++it) {
        int e = (tid + 256 * it) * 4;
        int row = e >> 6, col = e & 63;
        *(float4*)(io + base + (size_t)row * FSZ + col) = *(float4*)(smy + row * PADX + col);
    }
}

// ---------------- launch ----------------
extern "C" void kernel_launch(void* const* d_in, const int* in_sizes, int n_in,
                              void* d_out, int out_size) {
    const float* x   = (const float*)d_in[0];
    const float* l1w = (const float*)d_in[1];
    const float* l1b = (const float*)d_in[2];
    const float* l2w = (const float*)d_in[3];
    const float* l2b = (const float*)d_in[4];
    const float* W1  = (const float*)d_in[5];
    const float* b1  = (const float*)d_in[6];
    const float* dww = (const float*)d_in[7];
    const float* dwb = (const float*)d_in[8];
    const float* aw1 = (const float*)d_in[9];
    const float* ab1 = (const float*)d_in[10];
    const float* aw2 = (const float*)d_in[11];
    const float* ab2 = (const float*)d_in[12];
    const float* W2  = (const float*)d_in[13];
    const float* b2  = (const float*)d_in[14];
    const float* W3  = (const float*)d_in[15];
    const float* b3  = (const float*)d_in[16];
    const float* W4  = (const float*)d_in[17];
    const float* b4  = (const float*)d_in[18];
    float* out = (float*)d_out;

    k_init  <<<5, 256>>>(W1, W2, W3, W4);
    k_stats1<<<NB * 512, 256>>>(x);
    k_br1   <<<NB * 1024, 256>>>(x, l1w, l1b, b1, dww, dwb);
    k_y     <<<NB * 1024, 256>>>(x, b2, aw1, ab1, aw2, ab2, out);
    k_br2   <<<NB * 1024, 256>>>(l2w, l2b, b3, b4, out);
}